// round 1
// baseline (speedup 1.0000x reference)
#include <cuda_runtime.h>
#include <math.h>

// Problem constants
#define LNUM 6
#define BB   8
#define TT   1024
#define SS   1024
#define EE   1024
#define HH   16
#define HDIM 64
#define FF   4096
#define MROWS (BB*TT)      // 8192 token rows
#define LN_EPS 1e-5f

// ---------------------------------------------------------------------------
// Scratch (device globals; no allocation allowed)
// ---------------------------------------------------------------------------
__device__ float g_nx  [(size_t)MROWS*EE];
__device__ float g_q   [(size_t)MROWS*EE];
__device__ float g_k   [(size_t)MROWS*EE];
__device__ float g_v   [(size_t)MROWS*EE];
__device__ float g_attn[(size_t)MROWS*EE];
__device__ float g_ffn [(size_t)MROWS*FF];

// ---------------------------------------------------------------------------
// LayerNorm: one block per row of E=1024, 256 threads (4 floats/thread)
// ---------------------------------------------------------------------------
__global__ void __launch_bounds__(256) layernorm_kernel(
    const float* __restrict__ x, const float* __restrict__ w,
    const float* __restrict__ b, float* __restrict__ out)
{
    const int row = blockIdx.x;
    const int tid = threadIdx.x;
    const float4* xr = (const float4*)(x + (size_t)row * EE);
    float4 xv = xr[tid];
    float s  = xv.x + xv.y + xv.z + xv.w;
    float sq = xv.x*xv.x + xv.y*xv.y + xv.z*xv.z + xv.w*xv.w;
    #pragma unroll
    for (int o = 16; o > 0; o >>= 1) {
        s  += __shfl_down_sync(0xffffffffu, s,  o);
        sq += __shfl_down_sync(0xffffffffu, sq, o);
    }
    __shared__ float ss[8], ssq[8];
    __shared__ float mean_s, rstd_s;
    const int wid = tid >> 5, lane = tid & 31;
    if (lane == 0) { ss[wid] = s; ssq[wid] = sq; }
    __syncthreads();
    if (tid == 0) {
        float ts = 0.f, tq = 0.f;
        #pragma unroll
        for (int i = 0; i < 8; i++) { ts += ss[i]; tq += ssq[i]; }
        float m   = ts * (1.f / EE);
        float var = tq * (1.f / EE) - m * m;
        mean_s = m;
        rstd_s = rsqrtf(var + LN_EPS);
    }
    __syncthreads();
    const float m = mean_s, r = rstd_s;
    float4 wv = ((const float4*)w)[tid];
    float4 bv = ((const float4*)b)[tid];
    float4 o;
    o.x = (xv.x - m) * r * wv.x + bv.x;
    o.y = (xv.y - m) * r * wv.y + bv.y;
    o.z = (xv.z - m) * r * wv.z + bv.z;
    o.w = (xv.w - m) * r * wv.w + bv.w;
    ((float4*)(out + (size_t)row * EE))[tid] = o;
}

// ---------------------------------------------------------------------------
// SGEMM: C[M,N] = A[M,K] @ B[K,N] with epilogue.
// EPI 0: C = acc
// EPI 1: C = gelu(acc + bias)          (tanh approximation, matching jax)
// EPI 2: C = C + acc + bias            (residual accumulate in place)
// 128x128 block tile, BK=16, 256 threads, 8x8 per-thread tile.
// Requires M%128==0, N%128==0, K%16==0 (true for all shapes here).
// ---------------------------------------------------------------------------
__device__ __forceinline__ float gelu_tanh(float x) {
    float x3 = x * x * x;
    return 0.5f * x * (1.f + tanhf(0.79788456080286535588f * (x + 0.044715f * x3)));
}

template<int EPI>
__global__ void __launch_bounds__(256) sgemm_kernel(
    const float* __restrict__ A, const float* __restrict__ Bm,
    const float* __restrict__ bias, float* __restrict__ C,
    int M, int N, int K)
{
    __shared__ float As[16][128];
    __shared__ float Bs[16][128];

    const int tid = threadIdx.x;
    const int bx = blockIdx.x, by = blockIdx.y;
    const int tx = tid & 15, ty = tid >> 4;

    float acc[8][8];
    #pragma unroll
    for (int i = 0; i < 8; i++)
        #pragma unroll
        for (int j = 0; j < 8; j++) acc[i][j] = 0.f;

    for (int k0 = 0; k0 < K; k0 += 16) {
        // load A tile (128x16), transposed into As[k][m]
        #pragma unroll
        for (int i = 0; i < 2; i++) {
            int idx = tid + i * 256;              // 0..511
            int ar = idx >> 2, ac4 = idx & 3;
            float4 av = *(const float4*)&A[(size_t)(by * 128 + ar) * K + k0 + ac4 * 4];
            As[ac4 * 4 + 0][ar] = av.x;
            As[ac4 * 4 + 1][ar] = av.y;
            As[ac4 * 4 + 2][ar] = av.z;
            As[ac4 * 4 + 3][ar] = av.w;
            int br = idx >> 5, bc4 = idx & 31;
            float4 bv = *(const float4*)&Bm[(size_t)(k0 + br) * N + bx * 128 + bc4 * 4];
            *(float4*)&Bs[br][bc4 * 4] = bv;
        }
        __syncthreads();
        #pragma unroll
        for (int kk = 0; kk < 16; kk++) {
            float a[8], b[8];
            #pragma unroll
            for (int i = 0; i < 8; i++) a[i] = As[kk][ty * 8 + i];
            #pragma unroll
            for (int j = 0; j < 8; j++) b[j] = Bs[kk][tx * 8 + j];
            #pragma unroll
            for (int i = 0; i < 8; i++)
                #pragma unroll
                for (int j = 0; j < 8; j++)
                    acc[i][j] += a[i] * b[j];
        }
        __syncthreads();
    }

    const int col0 = bx * 128 + tx * 8;
    float bia[8];
    if (EPI != 0) {
        #pragma unroll
        for (int j = 0; j < 8; j++) bia[j] = bias[col0 + j];
    }
    #pragma unroll
    for (int i = 0; i < 8; i++) {
        size_t r = (size_t)(by * 128 + ty * 8 + i);
        float* cp = C + r * N + col0;
        if (EPI == 0) {
            float4 v0 = make_float4(acc[i][0], acc[i][1], acc[i][2], acc[i][3]);
            float4 v1 = make_float4(acc[i][4], acc[i][5], acc[i][6], acc[i][7]);
            ((float4*)cp)[0] = v0;
            ((float4*)cp)[1] = v1;
        } else if (EPI == 1) {
            float4 v0, v1;
            v0.x = gelu_tanh(acc[i][0] + bia[0]);
            v0.y = gelu_tanh(acc[i][1] + bia[1]);
            v0.z = gelu_tanh(acc[i][2] + bia[2]);
            v0.w = gelu_tanh(acc[i][3] + bia[3]);
            v1.x = gelu_tanh(acc[i][4] + bia[4]);
            v1.y = gelu_tanh(acc[i][5] + bia[5]);
            v1.z = gelu_tanh(acc[i][6] + bia[6]);
            v1.w = gelu_tanh(acc[i][7] + bia[7]);
            ((float4*)cp)[0] = v0;
            ((float4*)cp)[1] = v1;
        } else {
            float4 c0 = ((float4*)cp)[0];
            float4 c1 = ((float4*)cp)[1];
            c0.x += acc[i][0] + bia[0];
            c0.y += acc[i][1] + bia[1];
            c0.z += acc[i][2] + bia[2];
            c0.w += acc[i][3] + bia[3];
            c1.x += acc[i][4] + bia[4];
            c1.y += acc[i][5] + bia[5];
            c1.z += acc[i][6] + bia[6];
            c1.w += acc[i][7] + bia[7];
            ((float4*)cp)[0] = c0;
            ((float4*)cp)[1] = c1;
        }
    }
}

// ---------------------------------------------------------------------------
// Flash attention (fp32, online softmax). One thread = one q row.
// Q,K,V,O layout: [B, seq, H, HD] flattened (head-split of [B,seq,E]).
// grid: (T/128, H, B); block 128 threads. K/V streamed through 64-row SMEM tiles.
// ---------------------------------------------------------------------------
template<bool CAUSAL>
__global__ void __launch_bounds__(128) attn_kernel(
    const float* __restrict__ Q, const float* __restrict__ K,
    const float* __restrict__ V, float* __restrict__ O)
{
    __shared__ float Ks[64][64];
    __shared__ float Vs[64][64];

    const int b = blockIdx.z, h = blockIdx.y;
    const int q_idx = blockIdx.x * 128 + threadIdx.x;
    const float scale = 0.125f;  // 1/sqrt(64)

    float q[64];
    {
        const float4* qp = (const float4*)(Q + ((size_t)b * TT + q_idx) * EE + h * HDIM);
        #pragma unroll
        for (int i = 0; i < 16; i++) {
            float4 t = qp[i];
            q[i*4+0] = t.x; q[i*4+1] = t.y; q[i*4+2] = t.z; q[i*4+3] = t.w;
        }
    }

    float m = -1e30f, l = 0.f;
    float acc[64];
    #pragma unroll
    for (int d = 0; d < 64; d++) acc[d] = 0.f;

    const int kend = CAUSAL ? (blockIdx.x * 128 + 128) : SS;

    for (int kt = 0; kt < kend; kt += 64) {
        __syncthreads();
        #pragma unroll
        for (int i = 0; i < 8; i++) {
            int idx = threadIdx.x + i * 128;          // 0..1023
            int r = idx >> 4, c4 = idx & 15;
            const float4* kp = (const float4*)(K + ((size_t)b * SS + kt + r) * EE + h * HDIM) + c4;
            const float4* vp = (const float4*)(V + ((size_t)b * SS + kt + r) * EE + h * HDIM) + c4;
            ((float4*)&Ks[r][0])[c4] = *kp;
            ((float4*)&Vs[r][0])[c4] = *vp;
        }
        __syncthreads();

        #pragma unroll 1
        for (int j = 0; j < 64; j++) {
            int kj = kt + j;
            if (CAUSAL && kj > q_idx) break;
            float s0 = 0.f, s1 = 0.f, s2 = 0.f, s3 = 0.f;
            #pragma unroll
            for (int d = 0; d < 64; d += 4) {
                s0 += q[d + 0] * Ks[j][d + 0];
                s1 += q[d + 1] * Ks[j][d + 1];
                s2 += q[d + 2] * Ks[j][d + 2];
                s3 += q[d + 3] * Ks[j][d + 3];
            }
            float s = ((s0 + s1) + (s2 + s3)) * scale;
            if (s > m) {
                float corr = __expf(m - s);
                l *= corr;
                #pragma unroll
                for (int d = 0; d < 64; d++) acc[d] *= corr;
                m = s;
            }
            float p = __expf(s - m);
            l += p;
            #pragma unroll
            for (int d = 0; d < 64; d++) acc[d] += p * Vs[j][d];
        }
    }

    const float inv = 1.f / l;
    float4* op = (float4*)(O + ((size_t)b * TT + q_idx) * EE + h * HDIM);
    #pragma unroll
    for (int i = 0; i < 16; i++) {
        float4 t;
        t.x = acc[i*4+0] * inv; t.y = acc[i*4+1] * inv;
        t.z = acc[i*4+2] * inv; t.w = acc[i*4+3] * inv;
        op[i] = t;
    }
}

// ---------------------------------------------------------------------------
// Launch
// ---------------------------------------------------------------------------
static inline void run_gemm(int epi, const float* A, const float* B,
                            const float* bias, float* C, int M, int N, int K)
{
    dim3 grid(N / 128, M / 128);
    if (epi == 0)      sgemm_kernel<0><<<grid, 256>>>(A, B, bias, C, M, N, K);
    else if (epi == 1) sgemm_kernel<1><<<grid, 256>>>(A, B, bias, C, M, N, K);
    else               sgemm_kernel<2><<<grid, 256>>>(A, B, bias, C, M, N, K);
}

extern "C" void kernel_launch(void* const* d_in, const int* in_sizes, int n_in,
                              void* d_out, int out_size)
{
    const float* enc   = (const float*)d_in[0];   // [B,S,E]
    const float* dec   = (const float*)d_in[1];   // [B,T,E]
    const float* ln1_w = (const float*)d_in[2];
    const float* ln1_b = (const float*)d_in[3];
    const float* ln2_w = (const float*)d_in[4];
    const float* ln2_b = (const float*)d_in[5];
    const float* ln3_w = (const float*)d_in[6];
    const float* ln3_b = (const float*)d_in[7];
    const float* Wq_s  = (const float*)d_in[8];
    const float* Wk_s  = (const float*)d_in[9];
    const float* Wv_s  = (const float*)d_in[10];
    const float* Wo_s  = (const float*)d_in[11];
    const float* bo_s  = (const float*)d_in[12];
    const float* Wq_c  = (const float*)d_in[13];
    const float* Wk_c  = (const float*)d_in[14];
    const float* Wv_c  = (const float*)d_in[15];
    const float* Wo_c  = (const float*)d_in[16];
    const float* bo_c  = (const float*)d_in[17];
    const float* W1    = (const float*)d_in[18];
    const float* b1    = (const float*)d_in[19];
    const float* W2    = (const float*)d_in[20];
    const float* b2    = (const float*)d_in[21];

    float *nx, *q, *k, *v, *attn, *ffn;
    cudaGetSymbolAddress((void**)&nx,   g_nx);
    cudaGetSymbolAddress((void**)&q,    g_q);
    cudaGetSymbolAddress((void**)&k,    g_k);
    cudaGetSymbolAddress((void**)&v,    g_v);
    cudaGetSymbolAddress((void**)&attn, g_attn);
    cudaGetSymbolAddress((void**)&ffn,  g_ffn);

    float* x = (float*)d_out;   // residual stream lives in d_out

    cudaMemcpyAsync(x, dec, (size_t)MROWS * EE * sizeof(float),
                    cudaMemcpyDeviceToDevice);

    const dim3 attn_grid(TT / 128, HH, BB);

    for (int l = 0; l < LNUM; l++) {
        const size_t wE = (size_t)l * EE * EE;
        const size_t wF1 = (size_t)l * EE * FF;
        const size_t wF2 = (size_t)l * FF * EE;

        // ---- self attention ----
        layernorm_kernel<<<MROWS, 256>>>(x, ln1_w + l * EE, ln1_b + l * EE, nx);
        run_gemm(0, nx, Wq_s + wE, nullptr, q, MROWS, EE, EE);
        run_gemm(0, nx, Wk_s + wE, nullptr, k, MROWS, EE, EE);
        run_gemm(0, nx, Wv_s + wE, nullptr, v, MROWS, EE, EE);
        attn_kernel<true><<<attn_grid, 128>>>(q, k, v, attn);
        run_gemm(2, attn, Wo_s + wE, bo_s + l * EE, x, MROWS, EE, EE);

        // ---- cross attention ----
        layernorm_kernel<<<MROWS, 256>>>(x, ln2_w + l * EE, ln2_b + l * EE, nx);
        run_gemm(0, nx,  Wq_c + wE, nullptr, q, MROWS, EE, EE);
        run_gemm(0, enc, Wk_c + wE, nullptr, k, MROWS, EE, EE);
        run_gemm(0, enc, Wv_c + wE, nullptr, v, MROWS, EE, EE);
        attn_kernel<false><<<attn_grid, 128>>>(q, k, v, attn);
        run_gemm(2, attn, Wo_c + wE, bo_c + l * EE, x, MROWS, EE, EE);

        // ---- FFN ----
        layernorm_kernel<<<MROWS, 256>>>(x, ln3_w + l * EE, ln3_b + l * EE, nx);
        run_gemm(1, nx,  W1 + wF1, b1 + (size_t)l * FF, ffn, MROWS, FF, EE);
        run_gemm(2, ffn, W2 + wF2, b2 + (size_t)l * EE, x,   MROWS, EE, FF);
    }
}

// round 5
// speedup vs baseline: 1.6004x; 1.6004x over previous
#include <cuda_runtime.h>
#include <cuda_bf16.h>
#include <cstdint>
#include <math.h>

typedef unsigned int u32;

// Problem constants
#define LNUM 6
#define BB   8
#define TT   1024
#define SS   1024
#define EE   1024
#define HH   16
#define HDIM 64
#define FF   4096
#define MROWS (BB*TT)
#define LN_EPS 1e-5f

// ---------------------------------------------------------------------------
// Scratch (device globals; no allocation allowed)
// ---------------------------------------------------------------------------
__device__ float g_nx  [(size_t)MROWS*EE];
__device__ float g_q   [(size_t)MROWS*EE];
__device__ float g_k   [(size_t)MROWS*EE];
__device__ float g_v   [(size_t)MROWS*EE];
__device__ float g_attn[(size_t)MROWS*EE];
__device__ float g_ffn [(size_t)MROWS*FF];

// ---------------------------------------------------------------------------
// LayerNorm: one block per row of E=1024, 256 threads
// ---------------------------------------------------------------------------
__global__ void __launch_bounds__(256) layernorm_kernel(
    const float* __restrict__ x, const float* __restrict__ w,
    const float* __restrict__ b, float* __restrict__ out)
{
    const int row = blockIdx.x;
    const int tid = threadIdx.x;
    const float4* xr = (const float4*)(x + (size_t)row * EE);
    float4 xv = xr[tid];
    float s  = xv.x + xv.y + xv.z + xv.w;
    float sq = xv.x*xv.x + xv.y*xv.y + xv.z*xv.z + xv.w*xv.w;
    #pragma unroll
    for (int o = 16; o > 0; o >>= 1) {
        s  += __shfl_down_sync(0xffffffffu, s,  o);
        sq += __shfl_down_sync(0xffffffffu, sq, o);
    }
    __shared__ float ss[8];
    __shared__ float ssq[8];
    __shared__ float mean_s, rstd_s;
    const int wid = tid >> 5;
    const int lane = tid & 31;
    if (lane == 0) { ss[wid] = s; ssq[wid] = sq; }
    __syncthreads();
    if (tid == 0) {
        float ts = 0.f, tq = 0.f;
        #pragma unroll
        for (int i = 0; i < 8; i++) { ts += ss[i]; tq += ssq[i]; }
        float m   = ts * (1.f / EE);
        float var = tq * (1.f / EE) - m * m;
        mean_s = m;
        rstd_s = rsqrtf(var + LN_EPS);
    }
    __syncthreads();
    const float m = mean_s;
    const float r = rstd_s;
    float4 wv = ((const float4*)w)[tid];
    float4 bv = ((const float4*)b)[tid];
    float4 o;
    o.x = (xv.x - m) * r * wv.x + bv.x;
    o.y = (xv.y - m) * r * wv.y + bv.y;
    o.z = (xv.z - m) * r * wv.z + bv.z;
    o.w = (xv.w - m) * r * wv.w + bv.w;
    ((float4*)(out + (size_t)row * EE))[tid] = o;
}

// ---------------------------------------------------------------------------
// Tensor-core GEMM: C[M,N] = A[M,K] @ B[K,N], bf16x3 decomposition.
// 128x128 CTA tile, BK=32, 256 threads (8 warps, each 32x64 tile).
// mma.sync.m16n8k16.bf16, fp32 accum: Ah*Bh + Ah*Bl + Al*Bh.
// EPI 0: C = acc ; EPI 1: C = gelu(acc+bias) ; EPI 2: C += acc + bias
// ---------------------------------------------------------------------------
#define A_STRIDE 40    // 32 bf16 + 8 pad  (80B rows, ldmatrix conflict-free)
#define B_STRIDE 136   // 128 bf16 + 8 pad (272B rows, ldmatrix conflict-free)

__device__ __forceinline__ float gelu_tanh(float x) {
    float x3 = x * x * x;
    return 0.5f * x * (1.f + tanhf(0.79788456080286535588f * (x + 0.044715f * x3)));
}

__device__ __forceinline__ void ldsm_x4(u32* r, u32 a) {
    asm volatile("ldmatrix.sync.aligned.m8n8.x4.shared.b16 {%0,%1,%2,%3}, [%4];"
                 : "=r"(r[0]), "=r"(r[1]), "=r"(r[2]), "=r"(r[3]) : "r"(a));
}
__device__ __forceinline__ void ldsm_x4t(u32* r, u32 a) {
    asm volatile("ldmatrix.sync.aligned.m8n8.x4.trans.shared.b16 {%0,%1,%2,%3}, [%4];"
                 : "=r"(r[0]), "=r"(r[1]), "=r"(r[2]), "=r"(r[3]) : "r"(a));
}
__device__ __forceinline__ void mma_bf16(float* c, const u32* a, u32 b0, u32 b1) {
    asm volatile(
        "mma.sync.aligned.m16n8k16.row.col.f32.bf16.bf16.f32 "
        "{%0,%1,%2,%3}, {%4,%5,%6,%7}, {%8,%9}, {%0,%1,%2,%3};"
        : "+f"(c[0]), "+f"(c[1]), "+f"(c[2]), "+f"(c[3])
        : "r"(a[0]), "r"(a[1]), "r"(a[2]), "r"(a[3]), "r"(b0), "r"(b1));
}

template<int EPI>
__global__ void __launch_bounds__(256, 1) tgemm_kernel(
    const float* __restrict__ A, const float* __restrict__ Bm,
    const float* __restrict__ bias, float* __restrict__ C,
    int M, int N, int K)
{
    __shared__ __nv_bfloat16 Ah[128 * A_STRIDE];
    __shared__ __nv_bfloat16 Al[128 * A_STRIDE];
    __shared__ __nv_bfloat16 Bh[32 * B_STRIDE];
    __shared__ __nv_bfloat16 Bl[32 * B_STRIDE];

    const int tid  = threadIdx.x;
    const int lane = tid & 31;
    const int wid  = tid >> 5;
    const int wm = wid & 3;          // warp grid 4 (M) x 2 (N)
    const int wn = wid >> 2;
    const int bx = blockIdx.x;
    const int by = blockIdx.y;

    float acc[2][8][4];
    #pragma unroll
    for (int i = 0; i < 2; i++) {
        #pragma unroll
        for (int j = 0; j < 8; j++) {
            #pragma unroll
            for (int q = 0; q < 4; q++) acc[i][j][q] = 0.f;
        }
    }

    const int g  = lane >> 3;
    const int lr = lane & 7;
    const int m0 = wm * 32;
    const int n0 = wn * 64;
    const u32 AhBase = (u32)__cvta_generic_to_shared(Ah);
    const u32 AlBase = (u32)__cvta_generic_to_shared(Al);
    const u32 BhBase = (u32)__cvta_generic_to_shared(Bh);
    const u32 BlBase = (u32)__cvta_generic_to_shared(Bl);

    for (int k0 = 0; k0 < K; k0 += 32) {
        __syncthreads();
        // load + split A tile: 128 rows x 32 cols (floats)
        #pragma unroll
        for (int i = 0; i < 4; i++) {
            int idx = tid + i * 256;
            int ar = idx >> 3;
            int ac = idx & 7;
            float4 av = *(const float4*)&A[(size_t)(by * 128 + ar) * K + k0 + ac * 4];
            __nv_bfloat16 h0 = __float2bfloat16(av.x);
            __nv_bfloat16 h1 = __float2bfloat16(av.y);
            __nv_bfloat16 h2 = __float2bfloat16(av.z);
            __nv_bfloat16 h3 = __float2bfloat16(av.w);
            __nv_bfloat16 l0 = __float2bfloat16(av.x - __bfloat162float(h0));
            __nv_bfloat16 l1 = __float2bfloat16(av.y - __bfloat162float(h1));
            __nv_bfloat16 l2 = __float2bfloat16(av.z - __bfloat162float(h2));
            __nv_bfloat16 l3 = __float2bfloat16(av.w - __bfloat162float(h3));
            int o = ar * A_STRIDE + ac * 4;
            *(__nv_bfloat162*)&Ah[o]     = __halves2bfloat162(h0, h1);
            *(__nv_bfloat162*)&Ah[o + 2] = __halves2bfloat162(h2, h3);
            *(__nv_bfloat162*)&Al[o]     = __halves2bfloat162(l0, l1);
            *(__nv_bfloat162*)&Al[o + 2] = __halves2bfloat162(l2, l3);
        }
        // load + split B tile: 32 rows x 128 cols (floats)
        #pragma unroll
        for (int i = 0; i < 4; i++) {
            int idx = tid + i * 256;
            int br = idx >> 5;
            int bc = idx & 31;
            float4 bv = *(const float4*)&Bm[(size_t)(k0 + br) * N + bx * 128 + bc * 4];
            __nv_bfloat16 h0 = __float2bfloat16(bv.x);
            __nv_bfloat16 h1 = __float2bfloat16(bv.y);
            __nv_bfloat16 h2 = __float2bfloat16(bv.z);
            __nv_bfloat16 h3 = __float2bfloat16(bv.w);
            __nv_bfloat16 l0 = __float2bfloat16(bv.x - __bfloat162float(h0));
            __nv_bfloat16 l1 = __float2bfloat16(bv.y - __bfloat162float(h1));
            __nv_bfloat16 l2 = __float2bfloat16(bv.z - __bfloat162float(h2));
            __nv_bfloat16 l3 = __float2bfloat16(bv.w - __bfloat162float(h3));
            int o = br * B_STRIDE + bc * 4;
            *(__nv_bfloat162*)&Bh[o]     = __halves2bfloat162(h0, h1);
            *(__nv_bfloat162*)&Bh[o + 2] = __halves2bfloat162(h2, h3);
            *(__nv_bfloat162*)&Bl[o]     = __halves2bfloat162(l0, l1);
            *(__nv_bfloat162*)&Bl[o + 2] = __halves2bfloat162(l2, l3);
        }
        __syncthreads();

        #pragma unroll
        for (int ks = 0; ks < 32; ks += 16) {
            u32 fah[2][4], fal[2][4], fbh[4][4], fbl[4][4];
            #pragma unroll
            for (int mi = 0; mi < 2; mi++) {
                int row = m0 + mi * 16 + lr + (g & 1) * 8;
                int col = ks + (g >> 1) * 8;
                u32 ofs = (u32)(row * A_STRIDE + col) * 2u;
                ldsm_x4(fah[mi], AhBase + ofs);
                ldsm_x4(fal[mi], AlBase + ofs);
            }
            #pragma unroll
            for (int pj = 0; pj < 4; pj++) {
                int krow = ks + lr + (g & 1) * 8;
                int ncol = n0 + pj * 16 + (g >> 1) * 8;
                u32 ofs = (u32)(krow * B_STRIDE + ncol) * 2u;
                ldsm_x4t(fbh[pj], BhBase + ofs);
                ldsm_x4t(fbl[pj], BlBase + ofs);
            }
            #pragma unroll
            for (int mi = 0; mi < 2; mi++) {
                #pragma unroll
                for (int nj = 0; nj < 8; nj++) {
                    int pj = nj >> 1;
                    int hf = nj & 1;
                    mma_bf16(acc[mi][nj], fah[mi], fbh[pj][hf*2], fbh[pj][hf*2+1]);
                    mma_bf16(acc[mi][nj], fah[mi], fbl[pj][hf*2], fbl[pj][hf*2+1]);
                    mma_bf16(acc[mi][nj], fal[mi], fbh[pj][hf*2], fbh[pj][hf*2+1]);
                }
            }
        }
    }

    // Epilogue: row = lane>>2 (+8), cols = nj*8 + (lane&3)*2
    const int rbase = by * 128 + m0 + (lane >> 2);
    const int cbase = bx * 128 + n0 + (lane & 3) * 2;
    #pragma unroll
    for (int mi = 0; mi < 2; mi++) {
        #pragma unroll
        for (int nj = 0; nj < 8; nj++) {
            int col = cbase + nj * 8;
            float b0 = 0.f, b1 = 0.f;
            if (EPI != 0) { b0 = bias[col]; b1 = bias[col + 1]; }
            #pragma unroll
            for (int half = 0; half < 2; half++) {
                size_t r = (size_t)(rbase + mi * 16 + half * 8);
                float* cp = C + r * N + col;
                float v0 = acc[mi][nj][half * 2 + 0];
                float v1 = acc[mi][nj][half * 2 + 1];
                if (EPI == 0) {
                    *(float2*)cp = make_float2(v0, v1);
                } else if (EPI == 1) {
                    *(float2*)cp = make_float2(gelu_tanh(v0 + b0), gelu_tanh(v1 + b1));
                } else {
                    float2 c = *(float2*)cp;
                    c.x += v0 + b0;
                    c.y += v1 + b1;
                    *(float2*)cp = c;
                }
            }
        }
    }
}

// ---------------------------------------------------------------------------
// Flash attention (fp32, online softmax). One thread = one q row.
// ---------------------------------------------------------------------------
template<bool CAUSAL>
__global__ void __launch_bounds__(128) attn_kernel(
    const float* __restrict__ Q, const float* __restrict__ K,
    const float* __restrict__ V, float* __restrict__ O)
{
    __shared__ float Ks[64][64];
    __shared__ float Vs[64][64];

    const int b = blockIdx.z;
    const int h = blockIdx.y;
    const int q_idx = blockIdx.x * 128 + threadIdx.x;
    const float scale = 0.125f;

    float q[64];
    {
        const float4* qp = (const float4*)(Q + ((size_t)b * TT + q_idx) * EE + h * HDIM);
        #pragma unroll
        for (int i = 0; i < 16; i++) {
            float4 t = qp[i];
            q[i*4+0] = t.x; q[i*4+1] = t.y; q[i*4+2] = t.z; q[i*4+3] = t.w;
        }
    }

    float m = -1e30f, l = 0.f;
    float acc[64];
    #pragma unroll
    for (int d = 0; d < 64; d++) acc[d] = 0.f;

    const int kend = CAUSAL ? (blockIdx.x * 128 + 128) : SS;

    for (int kt = 0; kt < kend; kt += 64) {
        __syncthreads();
        #pragma unroll
        for (int i = 0; i < 8; i++) {
            int idx = threadIdx.x + i * 128;
            int r = idx >> 4;
            int c4 = idx & 15;
            const float4* kp = (const float4*)(K + ((size_t)b * SS + kt + r) * EE + h * HDIM) + c4;
            const float4* vp = (const float4*)(V + ((size_t)b * SS + kt + r) * EE + h * HDIM) + c4;
            ((float4*)&Ks[r][0])[c4] = *kp;
            ((float4*)&Vs[r][0])[c4] = *vp;
        }
        __syncthreads();

        #pragma unroll 1
        for (int j = 0; j < 64; j++) {
            int kj = kt + j;
            if (CAUSAL && kj > q_idx) break;
            float s0 = 0.f, s1 = 0.f, s2 = 0.f, s3 = 0.f;
            #pragma unroll
            for (int d = 0; d < 64; d += 4) {
                s0 += q[d + 0] * Ks[j][d + 0];
                s1 += q[d + 1] * Ks[j][d + 1];
                s2 += q[d + 2] * Ks[j][d + 2];
                s3 += q[d + 3] * Ks[j][d + 3];
            }
            float s = ((s0 + s1) + (s2 + s3)) * scale;
            if (s > m) {
                float corr = __expf(m - s);
                l *= corr;
                #pragma unroll
                for (int d = 0; d < 64; d++) acc[d] *= corr;
                m = s;
            }
            float p = __expf(s - m);
            l += p;
            #pragma unroll
            for (int d = 0; d < 64; d++) acc[d] += p * Vs[j][d];
        }
    }

    const float inv = 1.f / l;
    float4* op = (float4*)(O + ((size_t)b * TT + q_idx) * EE + h * HDIM);
    #pragma unroll
    for (int i = 0; i < 16; i++) {
        float4 t;
        t.x = acc[i*4+0] * inv;
        t.y = acc[i*4+1] * inv;
        t.z = acc[i*4+2] * inv;
        t.w = acc[i*4+3] * inv;
        op[i] = t;
    }
}

// ---------------------------------------------------------------------------
// Launch
// ---------------------------------------------------------------------------
static void run_gemm(int epi, const float* A, const float* B,
                     const float* bias, float* C, int M, int N, int K)
{
    dim3 grid(N / 128, M / 128);
    if (epi == 0) {
        tgemm_kernel<0><<<grid, 256>>>(A, B, bias, C, M, N, K);
    } else if (epi == 1) {
        tgemm_kernel<1><<<grid, 256>>>(A, B, bias, C, M, N, K);
    } else {
        tgemm_kernel<2><<<grid, 256>>>(A, B, bias, C, M, N, K);
    }
}

extern "C" void kernel_launch(void* const* d_in, const int* in_sizes, int n_in,
                              void* d_out, int out_size)
{
    const float* enc   = (const float*)d_in[0];
    const float* dec   = (const float*)d_in[1];
    const float* ln1_w = (const float*)d_in[2];
    const float* ln1_b = (const float*)d_in[3];
    const float* ln2_w = (const float*)d_in[4];
    const float* ln2_b = (const float*)d_in[5];
    const float* ln3_w = (const float*)d_in[6];
    const float* ln3_b = (const float*)d_in[7];
    const float* Wq_s  = (const float*)d_in[8];
    const float* Wk_s  = (const float*)d_in[9];
    const float* Wv_s  = (const float*)d_in[10];
    const float* Wo_s  = (const float*)d_in[11];
    const float* bo_s  = (const float*)d_in[12];
    const float* Wq_c  = (const float*)d_in[13];
    const float* Wk_c  = (const float*)d_in[14];
    const float* Wv_c  = (const float*)d_in[15];
    const float* Wo_c  = (const float*)d_in[16];
    const float* bo_c  = (const float*)d_in[17];
    const float* W1    = (const float*)d_in[18];
    const float* b1p   = (const float*)d_in[19];
    const float* W2    = (const float*)d_in[20];
    const float* b2p   = (const float*)d_in[21];

    float *nx, *q, *k, *v, *attn, *ffn;
    cudaGetSymbolAddress((void**)&nx,   g_nx);
    cudaGetSymbolAddress((void**)&q,    g_q);
    cudaGetSymbolAddress((void**)&k,    g_k);
    cudaGetSymbolAddress((void**)&v,    g_v);
    cudaGetSymbolAddress((void**)&attn, g_attn);
    cudaGetSymbolAddress((void**)&ffn,  g_ffn);

    float* x = (float*)d_out;

    cudaMemcpyAsync(x, dec, (size_t)MROWS * EE * sizeof(float),
                    cudaMemcpyDeviceToDevice);

    const dim3 attn_grid(TT / 128, HH, BB);

    for (int l = 0; l < LNUM; l++) {
        const size_t wE  = (size_t)l * EE * EE;
        const size_t wF1 = (size_t)l * EE * FF;
        const size_t wF2 = (size_t)l * FF * EE;

        // ---- self attention ----
        layernorm_kernel<<<MROWS, 256>>>(x, ln1_w + l * EE, ln1_b + l * EE, nx);
        run_gemm(0, nx, Wq_s + wE, 0, q, MROWS, EE, EE);
        run_gemm(0, nx, Wk_s + wE, 0, k, MROWS, EE, EE);
        run_gemm(0, nx, Wv_s + wE, 0, v, MROWS, EE, EE);
        attn_kernel<true><<<attn_grid, 128>>>(q, k, v, attn);
        run_gemm(2, attn, Wo_s + wE, bo_s + l * EE, x, MROWS, EE, EE);

        // ---- cross attention ----
        layernorm_kernel<<<MROWS, 256>>>(x, ln2_w + l * EE, ln2_b + l * EE, nx);
        run_gemm(0, nx,  Wq_c + wE, 0, q, MROWS, EE, EE);
        run_gemm(0, enc, Wk_c + wE, 0, k, MROWS, EE, EE);
        run_gemm(0, enc, Wv_c + wE, 0, v, MROWS, EE, EE);
        attn_kernel<false><<<attn_grid, 128>>>(q, k, v, attn);
        run_gemm(2, attn, Wo_c + wE, bo_c + l * EE, x, MROWS, EE, EE);

        // ---- FFN ----
        layernorm_kernel<<<MROWS, 256>>>(x, ln3_w + l * EE, ln3_b + l * EE, nx);
        run_gemm(1, nx,  W1 + wF1, b1p + (size_t)l * FF, ffn, MROWS, FF, EE);
        run_gemm(2, ffn, W2 + wF2, b2p + (size_t)l * EE, x,   MROWS, EE, FF);
    }
}